// round 1
// baseline (speedup 1.0000x reference)
#include <cuda_runtime.h>
#include <cuda_bf16.h>
#include <cstdint>

// Problem constants
#define BB 2
#define LL 1024
#define HH 2048
#define II 4096
#define NN 16
#define RR 128
#define KK 4
#define BL (BB*LL)          // 2048 rows
#define SSMW (RR + 2*NN)    // 160

// Scratch (device globals; allocation-free)
__device__ float g_proj[(size_t)BL * 2 * II];   // [BL, 8192]  h_in | gate
__device__ float g_u   [(size_t)BL * II];       // [BL, 4096]
__device__ float g_ssm [(size_t)BL * SSMW];     // [BL, 160]   ts | B | C
__device__ float g_dt  [(size_t)BL * II];       // [BL, 4096]
__device__ float g_y   [(size_t)BL * II];       // [BL, 4096]

// ---------------------------------------------------------------------------
// Generic SGEMM:  C[M,N] = A[M,K] * B[N,K]^T   (both row-major, inner dim K)
// Block tile 128x128, BK=16, 256 threads, 8x8 per thread.
// Requires: M % 128 == 0, K % 16 == 0, lda/ldb/ldc float4-aligned rows.
// N may be ragged (guards on B loads + C stores).
// EPI: 0 = none, 1 = softplus(acc + bias[n])
// ---------------------------------------------------------------------------
template<int EPI>
__global__ __launch_bounds__(256)
void sgemm_nt(const float* __restrict__ A, const float* __restrict__ B,
              float* __restrict__ C, const float* __restrict__ bias,
              int M, int N, int K, int lda, int ldb, int ldc)
{
    __shared__ float As[16][128];
    __shared__ float Bs[16][128];

    const int tid = threadIdx.x;
    const int tx = tid & 15;        // 0..15 -> n groups of 8
    const int ty = tid >> 4;        // 0..15 -> m groups of 8
    const int brow = blockIdx.y * 128;
    const int bcol = blockIdx.x * 128;

    const int lrow  = tid >> 2;          // 0..63
    const int lcol4 = (tid & 3) * 4;     // 0,4,8,12

    float acc[8][8];
#pragma unroll
    for (int i = 0; i < 8; ++i)
#pragma unroll
        for (int j = 0; j < 8; ++j) acc[i][j] = 0.f;

    for (int kt = 0; kt < K; kt += 16) {
        // Load A tile (M always multiple of 128 -> no guard)
#pragma unroll
        for (int p = 0; p < 2; ++p) {
            int r = lrow + p * 64;
            float4 v = *(const float4*)(A + (size_t)(brow + r) * lda + kt + lcol4);
            As[lcol4 + 0][r] = v.x;
            As[lcol4 + 1][r] = v.y;
            As[lcol4 + 2][r] = v.z;
            As[lcol4 + 3][r] = v.w;
        }
        // Load B tile (guard ragged N)
#pragma unroll
        for (int p = 0; p < 2; ++p) {
            int r = lrow + p * 64;
            int n = bcol + r;
            float4 v = make_float4(0.f, 0.f, 0.f, 0.f);
            if (n < N) v = *(const float4*)(B + (size_t)n * ldb + kt + lcol4);
            Bs[lcol4 + 0][r] = v.x;
            Bs[lcol4 + 1][r] = v.y;
            Bs[lcol4 + 2][r] = v.z;
            Bs[lcol4 + 3][r] = v.w;
        }
        __syncthreads();

#pragma unroll
        for (int k = 0; k < 16; ++k) {
            float a[8], b[8];
            *(float4*)(a)     = *(const float4*)&As[k][ty * 8];
            *(float4*)(a + 4) = *(const float4*)&As[k][ty * 8 + 4];
            *(float4*)(b)     = *(const float4*)&Bs[k][tx * 8];
            *(float4*)(b + 4) = *(const float4*)&Bs[k][tx * 8 + 4];
#pragma unroll
            for (int i = 0; i < 8; ++i)
#pragma unroll
                for (int j = 0; j < 8; ++j)
                    acc[i][j] += a[i] * b[j];
        }
        __syncthreads();
    }

    // Epilogue + store
#pragma unroll
    for (int i = 0; i < 8; ++i) {
        int m = brow + ty * 8 + i;
#pragma unroll
        for (int j = 0; j < 8; j += 4) {
            int n = bcol + tx * 8 + j;
            if (n < N) {
                float4 v;
                float r0 = acc[i][j + 0], r1 = acc[i][j + 1];
                float r2 = acc[i][j + 2], r3 = acc[i][j + 3];
                if (EPI == 1) {
                    float b0 = bias[n + 0], b1 = bias[n + 1];
                    float b2 = bias[n + 2], b3 = bias[n + 3];
                    r0 += b0; r1 += b1; r2 += b2; r3 += b3;
                    r0 = (r0 > 20.f) ? r0 : log1pf(__expf(r0));
                    r1 = (r1 > 20.f) ? r1 : log1pf(__expf(r1));
                    r2 = (r2 > 20.f) ? r2 : log1pf(__expf(r2));
                    r3 = (r3 > 20.f) ? r3 : log1pf(__expf(r3));
                }
                v.x = r0; v.y = r1; v.z = r2; v.w = r3;
                *(float4*)(C + (size_t)m * ldc + n) = v;
            }
        }
    }
}

// ---------------------------------------------------------------------------
// Causal depthwise conv (K=4, left pad 3) + bias + silu.
// h_in = g_proj[:, 0:I];  u -> g_u [BL, I]
// ---------------------------------------------------------------------------
__global__ __launch_bounds__(256)
void conv_silu_kernel(const float* __restrict__ conv_w, const float* __restrict__ conv_b)
{
    int idx = blockIdx.x * blockDim.x + threadIdx.x;
    if (idx >= BL * II) return;
    int i  = idx & (II - 1);
    int bl = idx >> 12;           // II = 4096 = 2^12
    int l  = bl & (LL - 1);

    float w0 = conv_w[i * 4 + 0];
    float w1 = conv_w[i * 4 + 1];
    float w2 = conv_w[i * 4 + 2];
    float w3 = conv_w[i * 4 + 3];

    const float* hp = g_proj + (size_t)bl * (2 * II) + i;  // h_in column i, row bl
    float acc = conv_b[i];
    if (l >= 3) acc += w0 * hp[-(ptrdiff_t)3 * 2 * II];
    if (l >= 2) acc += w1 * hp[-(ptrdiff_t)2 * 2 * II];
    if (l >= 1) acc += w2 * hp[-(ptrdiff_t)1 * 2 * II];
    acc += w3 * hp[0];

    float sig = 1.f / (1.f + __expf(-acc));
    g_u[idx] = acc * sig;
}

// ---------------------------------------------------------------------------
// Selective scan. One 16-lane group per (b,i); lane = state index n.
// Reads g_dt, g_u, gate (g_proj col I+i), B/C (g_ssm cols 128..160), A_log, D.
// Writes g_y = (sum_n h*C + D*u) * silu(gate).
// ---------------------------------------------------------------------------
__global__ __launch_bounds__(256)
void scan_kernel(const float* __restrict__ A_log, const float* __restrict__ D)
{
    int g = blockIdx.x * 16 + (threadIdx.x >> 4);   // group id: 0..8191
    int lane = threadIdx.x & 15;                    // state n
    int i = g & (II - 1);
    int b = g >> 12;

    float a_n  = -__expf(A_log[i * NN + lane]);
    float Dval = D[i];

    const float* dtp = g_dt + (size_t)b * LL * II + i;
    const float* up  = g_u  + (size_t)b * LL * II + i;
    const float* gp  = g_proj + (size_t)b * LL * (2 * II) + II + i;
    const float* sp  = g_ssm + (size_t)b * LL * SSMW;
    float* yp = g_y + (size_t)b * LL * II + i;

    float h = 0.f;
    for (int l = 0; l < LL; ++l) {
        float dt = dtp[(size_t)l * II];
        float u  = up [(size_t)l * II];
        float gt = gp [(size_t)l * 2 * II];
        float Bn = sp[(size_t)l * SSMW + RR + lane];
        float Cn = sp[(size_t)l * SSMW + RR + NN + lane];

        float dA = __expf(dt * a_n);
        h = dA * h + (dt * u) * Bn;
        float contrib = h * Cn;
        // reduce over 16 lanes
        contrib += __shfl_xor_sync(0xffffffffu, contrib, 8, 16);
        contrib += __shfl_xor_sync(0xffffffffu, contrib, 4, 16);
        contrib += __shfl_xor_sync(0xffffffffu, contrib, 2, 16);
        contrib += __shfl_xor_sync(0xffffffffu, contrib, 1, 16);
        if (lane == 0) {
            float y = contrib + Dval * u;
            float sg = gt / (1.f + __expf(-gt));
            yp[(size_t)l * II] = y * sg;
        }
    }
}

// ---------------------------------------------------------------------------
extern "C" void kernel_launch(void* const* d_in, const int* in_sizes, int n_in,
                              void* d_out, int out_size)
{
    const float* x         = (const float*)d_in[0];  // [B,L,H]
    const float* in_proj_w = (const float*)d_in[1];  // [2I,H]
    const float* conv_w    = (const float*)d_in[2];  // [I,1,K]
    const float* conv_b    = (const float*)d_in[3];  // [I]
    const float* x_proj_w  = (const float*)d_in[4];  // [R+2N, I]
    const float* dt_proj_w = (const float*)d_in[5];  // [I,R]
    const float* dt_proj_b = (const float*)d_in[6];  // [I]
    const float* A_log     = (const float*)d_in[7];  // [I,N]
    const float* Dw        = (const float*)d_in[8];  // [I]
    const float* out_proj_w= (const float*)d_in[9];  // [H,I]
    float* out = (float*)d_out;                      // [B,L,H]

    float *p_proj, *p_u, *p_ssm, *p_dt, *p_y;
    cudaGetSymbolAddress((void**)&p_proj, g_proj);
    cudaGetSymbolAddress((void**)&p_u,    g_u);
    cudaGetSymbolAddress((void**)&p_ssm,  g_ssm);
    cudaGetSymbolAddress((void**)&p_dt,   g_dt);
    cudaGetSymbolAddress((void**)&p_y,    g_y);

    // 1) proj = x @ in_proj_w^T   [2048, 8192]
    {
        dim3 grid((2 * II) / 128, BL / 128);
        sgemm_nt<0><<<grid, 256>>>(x, in_proj_w, p_proj, nullptr,
                                   BL, 2 * II, HH, HH, HH, 2 * II);
    }
    // 2) conv + silu -> u
    {
        int total = BL * II;
        conv_silu_kernel<<<(total + 255) / 256, 256>>>(conv_w, conv_b);
    }
    // 3) ssm = u @ x_proj_w^T   [2048, 160]
    {
        dim3 grid((SSMW + 127) / 128, BL / 128);
        sgemm_nt<0><<<grid, 256>>>(p_u, x_proj_w, p_ssm, nullptr,
                                   BL, SSMW, II, II, II, SSMW);
    }
    // 4) dt = softplus(ts @ dt_proj_w^T + b)   [2048, 4096]; ts = ssm[:, :128], lda=160
    {
        dim3 grid(II / 128, BL / 128);
        sgemm_nt<1><<<grid, 256>>>(p_ssm, dt_proj_w, p_dt, dt_proj_b,
                                   BL, II, RR, SSMW, RR, II);
    }
    // 5) selective scan -> y
    {
        scan_kernel<<<(BB * II) / 16, 256>>>(A_log, Dw);
    }
    // 6) out = y @ out_proj_w^T   [2048, 2048]
    {
        dim3 grid(HH / 128, BL / 128);
        sgemm_nt<0><<<grid, 256>>>(p_y, out_proj_w, out, nullptr,
                                   BL, HH, II, II, II, HH);
    }
}

// round 4
// speedup vs baseline: 2.1329x; 2.1329x over previous
#include <cuda_runtime.h>
#include <cstdint>

// ---------------- problem constants ----------------
#define BB 2
#define LL 1024
#define HH 2048
#define II 4096
#define NN 16
#define RR 128
#define BL (BB*LL)          // 2048
#define SSMW (RR + 2*NN)    // 160

// ---------------- scratch (device globals) ----------------
__device__ float g_proj[(size_t)BL * 2 * II];   // [BL, 8192] h_in | gate
__device__ float g_u   [(size_t)BL * II];       // [BL, 4096]
__device__ float g_ssm [(size_t)BL * SSMW];     // [BL, 160]
__device__ float g_dt  [(size_t)BL * II];       // [BL, 4096]
__device__ float g_y   [(size_t)BL * II];       // [BL, 4096]
__device__ float g_x32 [(size_t)BL * HH];       // tf32(x)
__device__ float g_w1  [(size_t)2 * II * HH];   // tf32(in_proj_w)
__device__ float g_wx  [(size_t)SSMW * II];     // tf32(x_proj_w)
__device__ float g_wdt [(size_t)II * RR];       // tf32(dt_proj_w)
__device__ float g_wo  [(size_t)HH * II];       // tf32(out_proj_w)

// ---------------- helpers ----------------
__device__ __forceinline__ uint32_t smem_u32(const void* p) {
    uint32_t a;
    asm("{ .reg .u64 t; cvta.to.shared.u64 t, %1; cvt.u32.u64 %0, t; }" : "=r"(a) : "l"(p));
    return a;
}
__device__ __forceinline__ float tf32r(float x) {
    uint32_t u;
    asm("cvt.rna.tf32.f32 %0, %1;" : "=r"(u) : "f"(x));
    return __uint_as_float(u);
}
__device__ __forceinline__ uint32_t swz(uint32_t off) {   // SW128: bits[6:4] ^= bits[9:7]
    return off ^ ((off >> 3) & 0x70);
}
#define CP_ASYNC16(dst, src) \
    asm volatile("cp.async.cg.shared.global [%0], [%1], 16;" :: "r"(dst), "l"(src) : "memory")
#define CP_COMMIT() asm volatile("cp.async.commit_group;" ::: "memory")
#define CP_WAIT0()  asm volatile("cp.async.wait_group 0;" ::: "memory")
#define CP_WAIT1()  asm volatile("cp.async.wait_group 1;" ::: "memory")

#define LDMATRIX_X4(r, addr) \
    asm volatile("ldmatrix.sync.aligned.m8n8.x4.shared.b16 {%0,%1,%2,%3}, [%4];" \
        : "=r"((r)[0]), "=r"((r)[1]), "=r"((r)[2]), "=r"((r)[3]) : "r"(addr))

#define MMA_TF32(d, a, b0, b1) \
    asm volatile("mma.sync.aligned.m16n8k8.row.col.f32.tf32.tf32.f32 " \
        "{%0,%1,%2,%3}, {%4,%5,%6,%7}, {%8,%9}, {%0,%1,%2,%3};" \
        : "+f"((d)[0]), "+f"((d)[1]), "+f"((d)[2]), "+f"((d)[3]) \
        : "r"((a)[0]), "r"((a)[1]), "r"((a)[2]), "r"((a)[3]), "r"(b0), "r"(b1))

// ---------------------------------------------------------------------------
// tf32 tensor-core GEMM:  C[M,N] = A[M,K] * B[N,K]^T   (row-major, inner K)
// CTA tile 128x128, BK=32, 256 threads (8 warps @ 32x64), double-buffer cp.async.
// M % 128 == 0, K % 32 == 0. N ragged (guards). lda/ldb rows 16B-aligned.
// EPI: 0=store, 1=softplus(acc+bias[n]), 2=store tf32-rounded
// ---------------------------------------------------------------------------
template<int EPI>
__global__ __launch_bounds__(256)
void mgemm(const float* __restrict__ A, const float* __restrict__ B,
           float* __restrict__ C, const float* __restrict__ bias,
           int N, int K, int lda, int ldb, int ldc)
{
    extern __shared__ __align__(1024) char smem[];
    constexpr int ATILE = 16384;                 // 128 rows x 128B
    constexpr int STAGE = 2 * ATILE;             // A + B
    const uint32_t sb = smem_u32(smem);
    const int tid = threadIdx.x;
    const int brow = blockIdx.y * 128;
    const int bcol = blockIdx.x * 128;

    auto load_tile = [&](int kt, int s) {
        uint32_t base = sb + s * STAGE;
        const float* Ab = A + (size_t)brow * lda + kt * 32;
#pragma unroll
        for (int i = 0; i < 4; ++i) {
            int t = tid + 256 * i;
            int r = t >> 3, c = (t & 7) * 16;
            CP_ASYNC16(base + swz(r * 128 + c), Ab + (size_t)r * lda + (c >> 2));
        }
        const float* Bb = B + (size_t)bcol * ldb + kt * 32;
        uint32_t bb = base + ATILE;
#pragma unroll
        for (int i = 0; i < 4; ++i) {
            int t = tid + 256 * i;
            int r = t >> 3, c = (t & 7) * 16;
            uint32_t d = bb + swz(r * 128 + c);
            if (bcol + r < N) {
                CP_ASYNC16(d, Bb + (size_t)r * ldb + (c >> 2));
            } else {
                *(float4*)(smem + (d - sb)) = make_float4(0.f, 0.f, 0.f, 0.f);
            }
        }
        CP_COMMIT();
    };

    const int nt = K / 32;
    float acc[2][8][4];
#pragma unroll
    for (int f = 0; f < 2; ++f)
#pragma unroll
        for (int n = 0; n < 8; ++n)
#pragma unroll
            for (int q = 0; q < 4; ++q) acc[f][n][q] = 0.f;

    const int w = tid >> 5, lane = tid & 31;
    const int wm = (w >> 1) * 32;           // warp M offset (4 warps along M)
    const int wn = (w & 1) * 64;            // warp N offset (2 warps along N)
    const int g = lane >> 3, rr = lane & 7; // ldmatrix lane mapping
    const int lrow = (g & 1) * 8 + rr;      // row within 16-row frag
    const int lbyte = (g >> 1) * 16;        // 0 or 16 (k half)

    load_tile(0, 0);

    for (int kt = 0; kt < nt; ++kt) {
        if (kt + 1 < nt) { load_tile(kt + 1, (kt + 1) & 1); CP_WAIT1(); }
        else             { CP_WAIT0(); }
        __syncthreads();
        uint32_t abase = sb + (kt & 1) * STAGE;
        uint32_t bbase = abase + ATILE;
#pragma unroll
        for (int ks = 0; ks < 4; ++ks) {
            uint32_t af[2][4], bf[4][4];
#pragma unroll
            for (int f = 0; f < 2; ++f)
                LDMATRIX_X4(af[f], abase + swz((wm + f * 16 + lrow) * 128 + ks * 32 + lbyte));
#pragma unroll
            for (int p = 0; p < 4; ++p)
                LDMATRIX_X4(bf[p], bbase + swz((wn + p * 16 + lrow) * 128 + ks * 32 + lbyte));
#pragma unroll
            for (int f = 0; f < 2; ++f)
#pragma unroll
                for (int p = 0; p < 4; ++p) {
                    MMA_TF32(acc[f][2 * p],     af[f], bf[p][0], bf[p][2]);
                    MMA_TF32(acc[f][2 * p + 1], af[f], bf[p][1], bf[p][3]);
                }
        }
        __syncthreads();
    }

    // epilogue
    const int gid = lane >> 2, tig = lane & 3;
#pragma unroll
    for (int f = 0; f < 2; ++f) {
#pragma unroll
        for (int nf = 0; nf < 8; ++nf) {
            int n = bcol + wn + nf * 8 + tig * 2;
            if (n >= N) continue;
            int m0 = brow + wm + f * 16 + gid;
            float v[4] = { acc[f][nf][0], acc[f][nf][1], acc[f][nf][2], acc[f][nf][3] };
            if (EPI == 1) {
#pragma unroll
                for (int q = 0; q < 4; ++q) {
                    float t = v[q] + bias[n + (q & 1)];
                    v[q] = (t > 20.f) ? t : log1pf(__expf(t));
                }
            }
            if (EPI == 2) {
#pragma unroll
                for (int q = 0; q < 4; ++q) v[q] = tf32r(v[q]);
            }
            *(float2*)(C + (size_t)m0 * ldc + n)       = make_float2(v[0], v[1]);
            *(float2*)(C + (size_t)(m0 + 8) * ldc + n) = make_float2(v[2], v[3]);
        }
    }
}

// ---------------------------------------------------------------------------
// tf32 rounding copy
// ---------------------------------------------------------------------------
__global__ __launch_bounds__(256)
void cvt_tf32_kernel(const float4* __restrict__ src, float4* __restrict__ dst, int n4)
{
    int i = blockIdx.x * blockDim.x + threadIdx.x;
    if (i < n4) {
        float4 v = src[i];
        v.x = tf32r(v.x); v.y = tf32r(v.y); v.z = tf32r(v.z); v.w = tf32r(v.w);
        dst[i] = v;
    }
}

// ---------------------------------------------------------------------------
// Causal depthwise conv (K=4) + bias + silu -> u (tf32-rounded)
// ---------------------------------------------------------------------------
__global__ __launch_bounds__(256)
void conv_silu_kernel(const float* __restrict__ conv_w, const float* __restrict__ conv_b)
{
    int idx = blockIdx.x * blockDim.x + threadIdx.x;
    if (idx >= BL * II) return;
    int i  = idx & (II - 1);
    int bl = idx >> 12;
    int l  = bl & (LL - 1);

    float w0 = conv_w[i * 4 + 0];
    float w1 = conv_w[i * 4 + 1];
    float w2 = conv_w[i * 4 + 2];
    float w3 = conv_w[i * 4 + 3];

    const float* hp = g_proj + (size_t)bl * (2 * II) + i;
    float acc = conv_b[i];
    if (l >= 3) acc += w0 * hp[-(ptrdiff_t)3 * 2 * II];
    if (l >= 2) acc += w1 * hp[-(ptrdiff_t)2 * 2 * II];
    if (l >= 1) acc += w2 * hp[-(ptrdiff_t)1 * 2 * II];
    acc += w3 * hp[0];

    float sig = 1.f / (1.f + __expf(-acc));
    g_u[idx] = tf32r(acc * sig);
}

// ---------------------------------------------------------------------------
// Selective scan -> y (tf32-rounded)
// ---------------------------------------------------------------------------
__global__ __launch_bounds__(256)
void scan_kernel(const float* __restrict__ A_log, const float* __restrict__ D)
{
    int g = blockIdx.x * 16 + (threadIdx.x >> 4);
    int lane = threadIdx.x & 15;
    int i = g & (II - 1);
    int b = g >> 12;

    float a_n  = -__expf(A_log[i * NN + lane]);
    float Dval = D[i];

    const float* dtp = g_dt + (size_t)b * LL * II + i;
    const float* up  = g_u  + (size_t)b * LL * II + i;
    const float* gp  = g_proj + (size_t)b * LL * (2 * II) + II + i;
    const float* sp  = g_ssm + (size_t)b * LL * SSMW;
    float* yp = g_y + (size_t)b * LL * II + i;

    float h = 0.f;
    for (int l = 0; l < LL; ++l) {
        float dt = dtp[(size_t)l * II];
        float u  = up [(size_t)l * II];
        float gt = gp [(size_t)l * 2 * II];
        float Bn = sp[(size_t)l * SSMW + RR + lane];
        float Cn = sp[(size_t)l * SSMW + RR + NN + lane];

        float dA = __expf(dt * a_n);
        h = dA * h + (dt * u) * Bn;
        float contrib = h * Cn;
        contrib += __shfl_xor_sync(0xffffffffu, contrib, 8, 16);
        contrib += __shfl_xor_sync(0xffffffffu, contrib, 4, 16);
        contrib += __shfl_xor_sync(0xffffffffu, contrib, 2, 16);
        contrib += __shfl_xor_sync(0xffffffffu, contrib, 1, 16);
        if (lane == 0) {
            float y = contrib + Dval * u;
            float sg = gt / (1.f + __expf(-gt));
            yp[(size_t)l * II] = tf32r(y * sg);
        }
    }
}

// ---------------------------------------------------------------------------
extern "C" void kernel_launch(void* const* d_in, const int* in_sizes, int n_in,
                              void* d_out, int out_size)
{
    const float* x          = (const float*)d_in[0];
    const float* in_proj_w  = (const float*)d_in[1];
    const float* conv_w     = (const float*)d_in[2];
    const float* conv_b     = (const float*)d_in[3];
    const float* x_proj_w   = (const float*)d_in[4];
    const float* dt_proj_w  = (const float*)d_in[5];
    const float* dt_proj_b  = (const float*)d_in[6];
    const float* A_log      = (const float*)d_in[7];
    const float* Dw         = (const float*)d_in[8];
    const float* out_proj_w = (const float*)d_in[9];
    float* out = (float*)d_out;

    float *p_proj, *p_u, *p_ssm, *p_dt, *p_y;
    float *p_x32, *p_w1, *p_wx, *p_wdt, *p_wo;
    cudaGetSymbolAddress((void**)&p_proj, g_proj);
    cudaGetSymbolAddress((void**)&p_u,    g_u);
    cudaGetSymbolAddress((void**)&p_ssm,  g_ssm);
    cudaGetSymbolAddress((void**)&p_dt,   g_dt);
    cudaGetSymbolAddress((void**)&p_y,    g_y);
    cudaGetSymbolAddress((void**)&p_x32,  g_x32);
    cudaGetSymbolAddress((void**)&p_w1,   g_w1);
    cudaGetSymbolAddress((void**)&p_wx,   g_wx);
    cudaGetSymbolAddress((void**)&p_wdt,  g_wdt);
    cudaGetSymbolAddress((void**)&p_wo,   g_wo);

    const int smem = 65536;
    cudaFuncSetAttribute(mgemm<0>, cudaFuncAttributeMaxDynamicSharedMemorySize, smem);
    cudaFuncSetAttribute(mgemm<1>, cudaFuncAttributeMaxDynamicSharedMemorySize, smem);
    cudaFuncSetAttribute(mgemm<2>, cudaFuncAttributeMaxDynamicSharedMemorySize, smem);

    // round GEMM inputs to tf32 (RN)
    auto cvt = [&](const float* s, float* d, size_t n) {
        int n4 = (int)(n / 4);
        cvt_tf32_kernel<<<(n4 + 255) / 256, 256>>>((const float4*)s, (float4*)d, n4);
    };
    cvt(x,          p_x32, (size_t)BL * HH);
    cvt(in_proj_w,  p_w1,  (size_t)2 * II * HH);
    cvt(x_proj_w,   p_wx,  (size_t)SSMW * II);
    cvt(dt_proj_w,  p_wdt, (size_t)II * RR);
    cvt(out_proj_w, p_wo,  (size_t)HH * II);

    // 1) proj = x @ in_proj_w^T   [2048, 8192], K=2048
    mgemm<0><<<dim3(2 * II / 128, BL / 128), 256, smem>>>(
        p_x32, p_w1, p_proj, nullptr, 2 * II, HH, HH, HH, 2 * II);
    // 2) conv + silu -> u
    conv_silu_kernel<<<(BL * II + 255) / 256, 256>>>(conv_w, conv_b);
    // 3) ssm = u @ x_proj_w^T   [2048, 160], K=4096 (tf32-rounded out)
    mgemm<2><<<dim3(2, BL / 128), 256, smem>>>(
        p_u, p_wx, p_ssm, nullptr, SSMW, II, II, II, SSMW);
    // 4) dt = softplus(ts @ dt_proj_w^T + bias)   [2048, 4096], K=128, lda=160
    mgemm<1><<<dim3(II / 128, BL / 128), 256, smem>>>(
        p_ssm, p_wdt, p_dt, dt_proj_b, II, RR, SSMW, RR, II);
    // 5) selective scan -> y
    scan_kernel<<<(BB * II) / 16, 256>>>(A_log, Dw);
    // 6) out = y @ out_proj_w^T   [2048, 2048], K=4096
    mgemm<0><<<dim3(HH / 128, BL / 128), 256, smem>>>(
        p_y, p_wo, out, nullptr, HH, II, II, II, HH);
}

// round 8
// speedup vs baseline: 2.2554x; 1.0574x over previous
#include <cuda_runtime.h>
#include <cstdint>

// ---------------- problem constants ----------------
#define BB 2
#define LL 1024
#define HH 2048
#define II 4096
#define NN 16
#define RR 128
#define BL (BB*LL)          // 2048
#define SSMW (RR + 2*NN)    // 160
#define SPLITK 8

// ---------------- scratch (device globals) ----------------
__device__ float g_proj[(size_t)BL * 2 * II];          // [BL, 8192] h_in | gate
__device__ float g_u   [(size_t)BL * II];              // [BL, 4096]
__device__ float g_part[(size_t)SPLITK * BL * SSMW];   // split-K partials
__device__ float g_ssm [(size_t)BL * SSMW];            // [BL, 160]
__device__ float g_dt  [(size_t)BL * II];              // [BL, 4096]
__device__ float g_y   [(size_t)BL * II];              // [BL, 4096]

// ---------------- helpers ----------------
__device__ __forceinline__ uint32_t smem_u32(const void* p) {
    uint32_t a;
    asm("{ .reg .u64 t; cvta.to.shared.u64 t, %1; cvt.u32.u64 %0, t; }" : "=r"(a) : "l"(p));
    return a;
}
__device__ __forceinline__ uint32_t tf32u(uint32_t x) {
    uint32_t u;
    asm("cvt.rna.tf32.f32 %0, %1;" : "=r"(u) : "r"(x));
    return u;
}
__device__ __forceinline__ uint32_t swz(uint32_t off) {   // SW128: bits[6:4] ^= bits[9:7]
    return off ^ ((off >> 3) & 0x70);
}
#define CP_ASYNC16(dst, src) \
    asm volatile("cp.async.cg.shared.global [%0], [%1], 16;" :: "r"(dst), "l"(src) : "memory")
#define CP_COMMIT() asm volatile("cp.async.commit_group;" ::: "memory")
#define CP_WAIT0()  asm volatile("cp.async.wait_group 0;" ::: "memory")
#define CP_WAIT1()  asm volatile("cp.async.wait_group 1;" ::: "memory")

#define LDMATRIX_X4(r, addr) \
    asm volatile("ldmatrix.sync.aligned.m8n8.x4.shared.b16 {%0,%1,%2,%3}, [%4];" \
        : "=r"((r)[0]), "=r"((r)[1]), "=r"((r)[2]), "=r"((r)[3]) : "r"(addr))

#define MMA_TF32(d, a, b0, b1) \
    asm volatile("mma.sync.aligned.m16n8k8.row.col.f32.tf32.tf32.f32 " \
        "{%0,%1,%2,%3}, {%4,%5,%6,%7}, {%8,%9}, {%0,%1,%2,%3};" \
        : "+f"((d)[0]), "+f"((d)[1]), "+f"((d)[2]), "+f"((d)[3]) \
        : "r"((a)[0]), "r"((a)[1]), "r"((a)[2]), "r"((a)[3]), "r"(b0), "r"(b1))

// ---------------------------------------------------------------------------
// tf32 tensor-core GEMM:  C[M,N] = A[M,K] * B[N,K]^T   (row-major, inner K)
// CTA tile 128x256, BK=32, 256 threads = 8 warps @ 64x64 (2 along M, 4 along N).
// Double-buffered cp.async. M % 128 == 0, K % 32 == 0, N ragged (guards).
// Fragments are rounded to tf32 (RNA) in registers after ldmatrix.
// Split-K via blockIdx.z: A += z*akz, B += z*akz (same k offset), C += z*ckz.
// EPI: 0 = store fp32, 1 = softplus(acc + bias[n])
// ---------------------------------------------------------------------------
template<int EPI>
__global__ __launch_bounds__(256)
void mgemm(const float* __restrict__ A, const float* __restrict__ B,
           float* __restrict__ C, const float* __restrict__ bias,
           int N, int K, int lda, int ldb, int ldc, int akz, long long ckz)
{
    extern __shared__ __align__(1024) char smem[];
    constexpr int ATILE = 128 * 128;             // 16 KB
    constexpr int BTILE = 256 * 128;             // 32 KB
    constexpr int STAGE = ATILE + BTILE;         // 48 KB
    const uint32_t sb = smem_u32(smem);
    const int tid = threadIdx.x;
    const int brow = blockIdx.y * 128;
    const int bcol = blockIdx.x * 256;

    A += (size_t)blockIdx.z * akz;
    B += (size_t)blockIdx.z * akz;    // same k-offset into B's K-major rows
    C += (size_t)blockIdx.z * ckz;

    auto load_tile = [&](int kt, int s) {
        uint32_t base = sb + s * STAGE;
        const float* Ab = A + (size_t)brow * lda + kt * 32;
#pragma unroll
        for (int i = 0; i < 4; ++i) {
            int t = tid + 256 * i;               // 0..1023
            int r = t >> 3, c = (t & 7) * 16;
            CP_ASYNC16(base + swz(r * 128 + c), Ab + (size_t)r * lda + (c >> 2));
        }
        const float* Bb = B + (size_t)bcol * ldb + kt * 32;
        uint32_t bb = base + ATILE;
#pragma unroll
        for (int i = 0; i < 8; ++i) {
            int t = tid + 256 * i;               // 0..2047
            int r = t >> 3, c = (t & 7) * 16;
            uint32_t d = bb + swz(r * 128 + c);
            if (bcol + r < N) {
                CP_ASYNC16(d, Bb + (size_t)r * ldb + (c >> 2));
            } else {
                *(float4*)(smem + (d - sb)) = make_float4(0.f, 0.f, 0.f, 0.f);
            }
        }
        CP_COMMIT();
    };

    const int nt = K / 32;
    float acc[4][8][4];
#pragma unroll
    for (int mf = 0; mf < 4; ++mf)
#pragma unroll
        for (int nf = 0; nf < 8; ++nf)
#pragma unroll
            for (int q = 0; q < 4; ++q) acc[mf][nf][q] = 0.f;

    const int w = tid >> 5, lane = tid & 31;
    const int wm = (w & 1) * 64;            // 2 warps along M
    const int wn = (w >> 1) * 64;           // 4 warps along N
    const int g = lane >> 3, rr = lane & 7; // ldmatrix lane mapping
    const int lrow = (g & 1) * 8 + rr;      // row within 16-row frag
    const int lbyte = (g >> 1) * 16;        // 0 or 16 (k half)

    load_tile(0, 0);

    for (int kt = 0; kt < nt; ++kt) {
        if (kt + 1 < nt) { load_tile(kt + 1, (kt + 1) & 1); CP_WAIT1(); }
        else             { CP_WAIT0(); }
        __syncthreads();
        uint32_t abase = sb + (kt & 1) * STAGE;
        uint32_t bbase = abase + ATILE;
#pragma unroll
        for (int ks = 0; ks < 4; ++ks) {
            uint32_t af[4][4], bf[4][4];
#pragma unroll
            for (int mf = 0; mf < 4; ++mf) {
                LDMATRIX_X4(af[mf], abase + swz((wm + mf * 16 + lrow) * 128 + ks * 32 + lbyte));
#pragma unroll
                for (int q = 0; q < 4; ++q) af[mf][q] = tf32u(af[mf][q]);
            }
#pragma unroll
            for (int p = 0; p < 4; ++p) {
                LDMATRIX_X4(bf[p], bbase + swz((wn + p * 16 + lrow) * 128 + ks * 32 + lbyte));
#pragma unroll
                for (int q = 0; q < 4; ++q) bf[p][q] = tf32u(bf[p][q]);
            }
#pragma unroll
            for (int mf = 0; mf < 4; ++mf)
#pragma unroll
                for (int p = 0; p < 4; ++p) {
                    MMA_TF32(acc[mf][2 * p],     af[mf], bf[p][0], bf[p][2]);
                    MMA_TF32(acc[mf][2 * p + 1], af[mf], bf[p][1], bf[p][3]);
                }
        }
        __syncthreads();
    }

    // epilogue
    const int gid = lane >> 2, tig = lane & 3;
#pragma unroll
    for (int mf = 0; mf < 4; ++mf) {
#pragma unroll
        for (int nf = 0; nf < 8; ++nf) {
            int n = bcol + wn + nf * 8 + tig * 2;
            if (n >= N) continue;
            int m0 = brow + wm + mf * 16 + gid;
            float v[4] = { acc[mf][nf][0], acc[mf][nf][1], acc[mf][nf][2], acc[mf][nf][3] };
            if (EPI == 1) {
#pragma unroll
                for (int q = 0; q < 4; ++q) {
                    float t = v[q] + bias[n + (q & 1)];
                    v[q] = (t > 20.f) ? t : log1pf(__expf(t));
                }
            }
            *(float2*)(C + (size_t)m0 * ldc + n)       = make_float2(v[0], v[1]);
            *(float2*)(C + (size_t)(m0 + 8) * ldc + n) = make_float2(v[2], v[3]);
        }
    }
}

// ---------------------------------------------------------------------------
// split-K reduce for ssm
// ---------------------------------------------------------------------------
__global__ __launch_bounds__(256)
void reduce_ssm_kernel()
{
    int i = blockIdx.x * blockDim.x + threadIdx.x;
    const int n = BL * SSMW;
    if (i < n) {
        float s = 0.f;
#pragma unroll
        for (int z = 0; z < SPLITK; ++z) s += g_part[(size_t)z * n + i];
        g_ssm[i] = s;
    }
}

// ---------------------------------------------------------------------------
// Causal depthwise conv (K=4) + bias + silu -> u
// ---------------------------------------------------------------------------
__global__ __launch_bounds__(256)
void conv_silu_kernel(const float* __restrict__ conv_w, const float* __restrict__ conv_b)
{
    int idx = blockIdx.x * blockDim.x + threadIdx.x;
    if (idx >= BL * II) return;
    int i  = idx & (II - 1);
    int bl = idx >> 12;
    int l  = bl & (LL - 1);

    float w0 = conv_w[i * 4 + 0];
    float w1 = conv_w[i * 4 + 1];
    float w2 = conv_w[i * 4 + 2];
    float w3 = conv_w[i * 4 + 3];

    const float* hp = g_proj + (size_t)bl * (2 * II) + i;
    float acc = conv_b[i];
    if (l >= 3) acc += w0 * hp[-(ptrdiff_t)3 * 2 * II];
    if (l >= 2) acc += w1 * hp[-(ptrdiff_t)2 * 2 * II];
    if (l >= 1) acc += w2 * hp[-(ptrdiff_t)1 * 2 * II];
    acc += w3 * hp[0];

    float sig = 1.f / (1.f + __expf(-acc));
    g_u[idx] = acc * sig;
}

// ---------------------------------------------------------------------------
// Selective scan -> y
// ---------------------------------------------------------------------------
__global__ __launch_bounds__(256)
void scan_kernel(const float* __restrict__ A_log, const float* __restrict__ D)
{
    int g = blockIdx.x * 16 + (threadIdx.x >> 4);
    int lane = threadIdx.x & 15;
    int i = g & (II - 1);
    int b = g >> 12;

    float a_n  = -__expf(A_log[i * NN + lane]);
    float Dval = D[i];

    const float* dtp = g_dt + (size_t)b * LL * II + i;
    const float* up  = g_u  + (size_t)b * LL * II + i;
    const float* gp  = g_proj + (size_t)b * LL * (2 * II) + II + i;
    const float* sp  = g_ssm + (size_t)b * LL * SSMW;
    float* yp = g_y + (size_t)b * LL * II + i;

    float h = 0.f;
    for (int l = 0; l < LL; ++l) {
        float dt = dtp[(size_t)l * II];
        float u  = up [(size_t)l * II];
        float gt = gp [(size_t)l * 2 * II];
        float Bn = sp[(size_t)l * SSMW + RR + lane];
        float Cn = sp[(size_t)l * SSMW + RR + NN + lane];

        float dA = __expf(dt * a_n);
        h = dA * h + (dt * u) * Bn;
        float contrib = h * Cn;
        contrib += __shfl_xor_sync(0xffffffffu, contrib, 8, 16);
        contrib += __shfl_xor_sync(0xffffffffu, contrib, 4, 16);
        contrib += __shfl_xor_sync(0xffffffffu, contrib, 2, 16);
        contrib += __shfl_xor_sync(0xffffffffu, contrib, 1, 16);
        if (lane == 0) {
            float y = contrib + Dval * u;
            float sg = gt / (1.f + __expf(-gt));
            yp[(size_t)l * II] = y * sg;
        }
    }
}

// ---------------------------------------------------------------------------
extern "C" void kernel_launch(void* const* d_in, const int* in_sizes, int n_in,
                              void* d_out, int out_size)
{
    const float* x          = (const float*)d_in[0];
    const float* in_proj_w  = (const float*)d_in[1];
    const float* conv_w     = (const float*)d_in[2];
    const float* conv_b     = (const float*)d_in[3];
    const float* x_proj_w   = (const float*)d_in[4];
    const float* dt_proj_w  = (const float*)d_in[5];
    const float* dt_proj_b  = (const float*)d_in[6];
    const float* A_log      = (const float*)d_in[7];
    const float* Dw         = (const float*)d_in[8];
    const float* out_proj_w = (const float*)d_in[9];
    float* out = (float*)d_out;

    float *p_proj, *p_u, *p_part, *p_ssm, *p_dt, *p_y;
    cudaGetSymbolAddress((void**)&p_proj, g_proj);
    cudaGetSymbolAddress((void**)&p_u,    g_u);
    cudaGetSymbolAddress((void**)&p_part, g_part);
    cudaGetSymbolAddress((void**)&p_ssm,  g_ssm);
    cudaGetSymbolAddress((void**)&p_dt,   g_dt);
    cudaGetSymbolAddress((void**)&p_y,    g_y);

    const int smem = 98304;   // 2 stages x 48 KB
    cudaFuncSetAttribute(mgemm<0>, cudaFuncAttributeMaxDynamicSharedMemorySize, smem);
    cudaFuncSetAttribute(mgemm<1>, cudaFuncAttributeMaxDynamicSharedMemorySize, smem);

    // 1) proj = x @ in_proj_w^T   [2048, 8192], K=2048
    mgemm<0><<<dim3(2 * II / 256, BL / 128, 1), 256, smem>>>(
        x, in_proj_w, p_proj, nullptr, 2 * II, HH, HH, HH, 2 * II, 0, 0);
    // 2) conv + silu -> u
    conv_silu_kernel<<<(BL * II + 255) / 256, 256>>>(conv_w, conv_b);
    // 3) ssm = u @ x_proj_w^T   [2048, 160], K=4096, split-K=8
    mgemm<0><<<dim3(1, BL / 128, SPLITK), 256, smem>>>(
        p_u, x_proj_w, p_part, nullptr, SSMW, II / SPLITK, II, II, SSMW,
        II / SPLITK, (long long)BL * SSMW);
    reduce_ssm_kernel<<<(BL * SSMW + 255) / 256, 256>>>();
    // 4) dt = softplus(ts @ dt_proj_w^T + bias)   [2048, 4096], K=128, lda=160
    mgemm<1><<<dim3(II / 256, BL / 128, 1), 256, smem>>>(
        p_ssm, dt_proj_w, p_dt, dt_proj_b, II, RR, SSMW, RR, II, 0, 0);
    // 5) selective scan -> y
    scan_kernel<<<(BB * II) / 16, 256>>>(A_log, Dw);
    // 6) out = y @ out_proj_w^T   [2048, 2048], K=4096
    mgemm<0><<<dim3(HH / 256, BL / 128, 1), 256, smem>>>(
        p_y, out_proj_w, out, nullptr, HH, II, II, II, HH, 0, 0);
}

// round 13
// speedup vs baseline: 2.9299x; 1.2991x over previous
#include <cuda_runtime.h>
#include <cuda_fp16.h>
#include <cstdint>

// ---------------- problem constants ----------------
#define BB 2
#define LL 1024
#define HH 2048
#define II 4096
#define NN 16
#define RR 128
#define BL (BB*LL)          // 2048
#define SSMW (RR + 2*NN)    // 160
#define SPLITK 8

// ---------------- scratch (device globals) ----------------
__device__ float  g_proj[(size_t)BL * 2 * II];          // [BL, 8192] h_in | gate (fp32)
__device__ float  g_u   [(size_t)BL * II];              // fp32 for scan
__device__ float  g_part[(size_t)SPLITK * BL * SSMW];   // split-K partials
__device__ float  g_ssm [(size_t)BL * SSMW];            // fp32 for scan (B, C)
__device__ float  g_dt  [(size_t)BL * II];              // fp32 for scan
__device__ __half h_x   [(size_t)BL * HH];              // fp16 inputs for GEMMs
__device__ __half h_w1  [(size_t)2 * II * HH];
__device__ __half h_wx  [(size_t)SSMW * II];
__device__ __half h_wdt [(size_t)II * RR];
__device__ __half h_wo  [(size_t)HH * II];
__device__ __half h_u   [(size_t)BL * II];
__device__ __half h_ssm [(size_t)BL * SSMW];
__device__ __half h_y   [(size_t)BL * II];

// ---------------- helpers ----------------
__device__ __forceinline__ uint32_t smem_u32(const void* p) {
    uint32_t a;
    asm("{ .reg .u64 t; cvta.to.shared.u64 t, %1; cvt.u32.u64 %0, t; }" : "=r"(a) : "l"(p));
    return a;
}
__device__ __forceinline__ uint32_t swz(uint32_t off) {   // SW128: bits[6:4] ^= bits[9:7]
    return off ^ ((off >> 3) & 0x70);
}
#define CP_ASYNC16(dst, src) \
    asm volatile("cp.async.cg.shared.global [%0], [%1], 16;" :: "r"(dst), "l"(src) : "memory")
#define CP_COMMIT() asm volatile("cp.async.commit_group;" ::: "memory")
#define CP_WAIT0()  asm volatile("cp.async.wait_group 0;" ::: "memory")
#define CP_WAIT1()  asm volatile("cp.async.wait_group 1;" ::: "memory")

#define LDMATRIX_X4(r, addr) \
    asm volatile("ldmatrix.sync.aligned.m8n8.x4.shared.b16 {%0,%1,%2,%3}, [%4];" \
        : "=r"((r)[0]), "=r"((r)[1]), "=r"((r)[2]), "=r"((r)[3]) : "r"(addr))

#define MMA_F16(d, a, b0, b1) \
    asm volatile("mma.sync.aligned.m16n8k16.row.col.f32.f16.f16.f32 " \
        "{%0,%1,%2,%3}, {%4,%5,%6,%7}, {%8,%9}, {%0,%1,%2,%3};" \
        : "+f"((d)[0]), "+f"((d)[1]), "+f"((d)[2]), "+f"((d)[3]) \
        : "r"((a)[0]), "r"((a)[1]), "r"((a)[2]), "r"((a)[3]), "r"(b0), "r"(b1))

// ---------------------------------------------------------------------------
// fp16 tensor-core GEMM:  C[M,N] = A[M,K] * B[N,K]^T  (fp16 in, fp32 accum/out)
// A, B row-major fp16 with inner dim K. CTA tile 128x256, BK=64 halves (128B),
// 256 threads = 8 warps @ 64x64. Double-buffered cp.async, SW128.
// M % 128 == 0, K % 64 == 0, N ragged. lda/ldb rows 16B aligned.
// Split-K: A += z*akz, B += z*akz (halves), C += z*ckz.
// EPI: 0 = store fp32, 1 = softplus(acc + bias[n])
// ---------------------------------------------------------------------------
template<int EPI>
__global__ __launch_bounds__(256)
void hgemm(const __half* __restrict__ A, const __half* __restrict__ B,
           float* __restrict__ C, const float* __restrict__ bias,
           int N, int K, int lda, int ldb, int ldc, int akz, long long ckz)
{
    extern __shared__ __align__(1024) char smem[];
    constexpr int ATILE = 128 * 128;             // 16 KB (128 rows x 128B)
    constexpr int BTILE = 256 * 128;             // 32 KB
    constexpr int STAGE = ATILE + BTILE;         // 48 KB
    const uint32_t sb = smem_u32(smem);
    const int tid = threadIdx.x;
    const int brow = blockIdx.y * 128;
    const int bcol = blockIdx.x * 256;

    A += (size_t)blockIdx.z * akz;
    B += (size_t)blockIdx.z * akz;
    C += (size_t)blockIdx.z * ckz;

    auto load_tile = [&](int kt, int s) {
        uint32_t base = sb + s * STAGE;
        const __half* Ab = A + (size_t)brow * lda + kt * 64;
#pragma unroll
        for (int i = 0; i < 4; ++i) {
            int t = tid + 256 * i;               // 0..1023 -> 128 rows x 8 chunks
            int r = t >> 3, c = (t & 7) * 16;    // byte col in 128B row
            CP_ASYNC16(base + swz(r * 128 + c), Ab + (size_t)r * lda + (c >> 1));
        }
        const __half* Bb = B + (size_t)bcol * ldb + kt * 64;
        uint32_t bb = base + ATILE;
#pragma unroll
        for (int i = 0; i < 8; ++i) {
            int t = tid + 256 * i;               // 0..2047 -> 256 rows
            int r = t >> 3, c = (t & 7) * 16;
            uint32_t d = bb + swz(r * 128 + c);
            if (bcol + r < N) {
                CP_ASYNC16(d, Bb + (size_t)r * ldb + (c >> 1));
            } else {
                *(float4*)(smem + (d - sb)) = make_float4(0.f, 0.f, 0.f, 0.f);
            }
        }
        CP_COMMIT();
    };

    const int nt = K / 64;
    float acc[4][8][4];
#pragma unroll
    for (int mf = 0; mf < 4; ++mf)
#pragma unroll
        for (int nf = 0; nf < 8; ++nf)
#pragma unroll
            for (int q = 0; q < 4; ++q) acc[mf][nf][q] = 0.f;

    const int w = tid >> 5, lane = tid & 31;
    const int wm = (w & 1) * 64;            // 2 warps along M
    const int wn = (w >> 1) * 64;           // 4 warps along N
    const int g = lane >> 3, rr = lane & 7;
    // A-frag lane map (m16k16): row in 16-row frag, k-byte half (0/16)
    const int arow = (g & 1) * 8 + rr;
    const int abyte = (g >> 1) * 16;
    // B-frag lane map (two n8-groups per x4): n-row in 16, k-byte half
    const int brw = (g >> 1) * 8 + rr;
    const int bbyte = (g & 1) * 16;

    load_tile(0, 0);

    for (int kt = 0; kt < nt; ++kt) {
        if (kt + 1 < nt) { load_tile(kt + 1, (kt + 1) & 1); CP_WAIT1(); }
        else             { CP_WAIT0(); }
        __syncthreads();
        uint32_t abase = sb + (kt & 1) * STAGE;
        uint32_t bbase = abase + ATILE;
#pragma unroll
        for (int ks = 0; ks < 4; ++ks) {        // 4 x k16 (32B each)
            uint32_t af[4][4], bf[4][4];
#pragma unroll
            for (int mf = 0; mf < 4; ++mf)
                LDMATRIX_X4(af[mf], abase + swz((wm + mf * 16 + arow) * 128 + ks * 32 + abyte));
#pragma unroll
            for (int pp = 0; pp < 4; ++pp)      // pairs of n8-groups (16 n each)
                LDMATRIX_X4(bf[pp], bbase + swz((wn + pp * 16 + brw) * 128 + ks * 32 + bbyte));
#pragma unroll
            for (int mf = 0; mf < 4; ++mf)
#pragma unroll
                for (int pp = 0; pp < 4; ++pp) {
                    MMA_F16(acc[mf][2 * pp],     af[mf], bf[pp][0], bf[pp][1]);
                    MMA_F16(acc[mf][2 * pp + 1], af[mf], bf[pp][2], bf[pp][3]);
                }
        }
        __syncthreads();
    }

    // epilogue
    const int gid = lane >> 2, tig = lane & 3;
#pragma unroll
    for (int mf = 0; mf < 4; ++mf) {
#pragma unroll
        for (int nf = 0; nf < 8; ++nf) {
            int n = bcol + wn + nf * 8 + tig * 2;
            if (n >= N) continue;
            int m0 = brow + wm + mf * 16 + gid;
            float v[4] = { acc[mf][nf][0], acc[mf][nf][1], acc[mf][nf][2], acc[mf][nf][3] };
            if (EPI == 1) {
#pragma unroll
                for (int q = 0; q < 4; ++q) {
                    float t = v[q] + bias[n + (q & 1)];
                    v[q] = (t > 20.f) ? t : log1pf(__expf(t));
                }
            }
            *(float2*)(C + (size_t)m0 * ldc + n)       = make_float2(v[0], v[1]);
            *(float2*)(C + (size_t)(m0 + 8) * ldc + n) = make_float2(v[2], v[3]);
        }
    }
}

// ---------------------------------------------------------------------------
// f32 -> f16 conversion
// ---------------------------------------------------------------------------
__global__ __launch_bounds__(256)
void cvt_f16_kernel(const float4* __restrict__ src, __half2* __restrict__ dst, int n4)
{
    int i = blockIdx.x * blockDim.x + threadIdx.x;
    if (i < n4) {
        float4 v = src[i];
        dst[2 * i]     = __floats2half2_rn(v.x, v.y);
        dst[2 * i + 1] = __floats2half2_rn(v.z, v.w);
    }
}

// ---------------------------------------------------------------------------
// split-K reduce for ssm (fp32 + fp16 outputs)
// ---------------------------------------------------------------------------
__global__ __launch_bounds__(256)
void reduce_ssm_kernel()
{
    int i = blockIdx.x * blockDim.x + threadIdx.x;
    const int n = BL * SSMW;
    if (i < n) {
        float s = 0.f;
#pragma unroll
        for (int z = 0; z < SPLITK; ++z) s += g_part[(size_t)z * n + i];
        g_ssm[i] = s;
        h_ssm[i] = __float2half_rn(s);
    }
}

// ---------------------------------------------------------------------------
// Causal depthwise conv (K=4) + bias + silu -> u (fp32 + fp16)
// ---------------------------------------------------------------------------
__global__ __launch_bounds__(256)
void conv_silu_kernel(const float* __restrict__ conv_w, const float* __restrict__ conv_b)
{
    int idx = blockIdx.x * blockDim.x + threadIdx.x;
    if (idx >= BL * II) return;
    int i  = idx & (II - 1);
    int bl = idx >> 12;
    int l  = bl & (LL - 1);

    float w0 = conv_w[i * 4 + 0];
    float w1 = conv_w[i * 4 + 1];
    float w2 = conv_w[i * 4 + 2];
    float w3 = conv_w[i * 4 + 3];

    const float* hp = g_proj + (size_t)bl * (2 * II) + i;
    float acc = conv_b[i];
    if (l >= 3) acc += w0 * hp[-(ptrdiff_t)3 * 2 * II];
    if (l >= 2) acc += w1 * hp[-(ptrdiff_t)2 * 2 * II];
    if (l >= 1) acc += w2 * hp[-(ptrdiff_t)1 * 2 * II];
    acc += w3 * hp[0];

    float sig = 1.f / (1.f + __expf(-acc));
    float v = acc * sig;
    g_u[idx] = v;
    h_u[idx] = __float2half_rn(v);
}

// ---------------------------------------------------------------------------
// Selective scan -> y (fp16 for GEMM6)
// ---------------------------------------------------------------------------
__global__ __launch_bounds__(256)
void scan_kernel(const float* __restrict__ A_log, const float* __restrict__ D)
{
    int g = blockIdx.x * 16 + (threadIdx.x >> 4);
    int lane = threadIdx.x & 15;
    int i = g & (II - 1);
    int b = g >> 12;

    float a_n  = -__expf(A_log[i * NN + lane]);
    float Dval = D[i];

    const float* dtp = g_dt + (size_t)b * LL * II + i;
    const float* up  = g_u  + (size_t)b * LL * II + i;
    const float* gp  = g_proj + (size_t)b * LL * (2 * II) + II + i;
    const float* sp  = g_ssm + (size_t)b * LL * SSMW;
    __half* yp = h_y + (size_t)b * LL * II + i;

    float h = 0.f;
    for (int l = 0; l < LL; ++l) {
        float dt = dtp[(size_t)l * II];
        float u  = up [(size_t)l * II];
        float gt = gp [(size_t)l * 2 * II];
        float Bn = sp[(size_t)l * SSMW + RR + lane];
        float Cn = sp[(size_t)l * SSMW + RR + NN + lane];

        float dA = __expf(dt * a_n);
        h = dA * h + (dt * u) * Bn;
        float contrib = h * Cn;
        contrib += __shfl_xor_sync(0xffffffffu, contrib, 8, 16);
        contrib += __shfl_xor_sync(0xffffffffu, contrib, 4, 16);
        contrib += __shfl_xor_sync(0xffffffffu, contrib, 2, 16);
        contrib += __shfl_xor_sync(0xffffffffu, contrib, 1, 16);
        if (lane == 0) {
            float y = contrib + Dval * u;
            float sg = gt / (1.f + __expf(-gt));
            yp[(size_t)l * II] = __float2half_rn(y * sg);
        }
    }
}

// ---------------------------------------------------------------------------
extern "C" void kernel_launch(void* const* d_in, const int* in_sizes, int n_in,
                              void* d_out, int out_size)
{
    const float* x          = (const float*)d_in[0];
    const float* in_proj_w  = (const float*)d_in[1];
    const float* conv_w     = (const float*)d_in[2];
    const float* conv_b     = (const float*)d_in[3];
    const float* x_proj_w   = (const float*)d_in[4];
    const float* dt_proj_w  = (const float*)d_in[5];
    const float* dt_proj_b  = (const float*)d_in[6];
    const float* A_log      = (const float*)d_in[7];
    const float* Dw         = (const float*)d_in[8];
    const float* out_proj_w = (const float*)d_in[9];
    float* out = (float*)d_out;

    float *p_proj, *p_part, *p_dt;
    __half *ph_x, *ph_w1, *ph_wx, *ph_wdt, *ph_wo, *ph_u, *ph_ssm, *ph_y;
    cudaGetSymbolAddress((void**)&p_proj, g_proj);
    cudaGetSymbolAddress((void**)&p_part, g_part);
    cudaGetSymbolAddress((void**)&p_dt,   g_dt);
    cudaGetSymbolAddress((void**)&ph_x,   h_x);
    cudaGetSymbolAddress((void**)&ph_w1,  h_w1);
    cudaGetSymbolAddress((void**)&ph_wx,  h_wx);
    cudaGetSymbolAddress((void**)&ph_wdt, h_wdt);
    cudaGetSymbolAddress((void**)&ph_wo,  h_wo);
    cudaGetSymbolAddress((void**)&ph_u,   h_u);
    cudaGetSymbolAddress((void**)&ph_ssm, h_ssm);
    cudaGetSymbolAddress((void**)&ph_y,   h_y);

    const int smem = 98304;   // 2 stages x 48 KB
    cudaFuncSetAttribute(hgemm<0>, cudaFuncAttributeMaxDynamicSharedMemorySize, smem);
    cudaFuncSetAttribute(hgemm<1>, cudaFuncAttributeMaxDynamicSharedMemorySize, smem);

    // convert GEMM inputs to fp16 (RN)
    auto cvt = [&](const float* s, __half* d, size_t n) {
        int n4 = (int)(n / 4);
        cvt_f16_kernel<<<(n4 + 255) / 256, 256>>>((const float4*)s, (__half2*)d, n4);
    };
    cvt(x,          ph_x,   (size_t)BL * HH);
    cvt(in_proj_w,  ph_w1,  (size_t)2 * II * HH);
    cvt(x_proj_w,   ph_wx,  (size_t)SSMW * II);
    cvt(dt_proj_w,  ph_wdt, (size_t)II * RR);
    cvt(out_proj_w, ph_wo,  (size_t)HH * II);

    // 1) proj = x @ in_proj_w^T   [2048, 8192], K=2048
    hgemm<0><<<dim3(2 * II / 256, BL / 128, 1), 256, smem>>>(
        ph_x, ph_w1, p_proj, nullptr, 2 * II, HH, HH, HH, 2 * II, 0, 0);
    // 2) conv + silu -> u (fp32 + fp16)
    conv_silu_kernel<<<(BL * II + 255) / 256, 256>>>(conv_w, conv_b);
    // 3) ssm = u @ x_proj_w^T   [2048, 160], K=4096, split-K=8
    hgemm<0><<<dim3(1, BL / 128, SPLITK), 256, smem>>>(
        ph_u, ph_wx, p_part, nullptr, SSMW, II / SPLITK, II, II, SSMW,
        II / SPLITK, (long long)BL * SSMW);
    reduce_ssm_kernel<<<(BL * SSMW + 255) / 256, 256>>>();
    // 4) dt = softplus(ts @ dt_proj_w^T + bias)   [2048, 4096], K=128, lda=160
    hgemm<1><<<dim3(II / 256, BL / 128, 1), 256, smem>>>(
        ph_ssm, ph_wdt, p_dt, dt_proj_b, II, RR, SSMW, RR, II, 0, 0);
    // 5) selective scan -> y (fp16)
    scan_kernel<<<(BB * II) / 16, 256>>>(A_log, Dw);
    // 6) out = y @ out_proj_w^T   [2048, 2048], K=4096
    hgemm<0><<<dim3(HH / 256, BL / 128, 1), 256, smem>>>(
        ph_y, ph_wo, out, nullptr, HH, II, II, II, HH, 0, 0);
}

// round 14
// speedup vs baseline: 2.9421x; 1.0042x over previous
#include <cuda_runtime.h>
#include <cuda_fp16.h>
#include <cstdint>

// ---------------- problem constants ----------------
#define BB 2
#define LL 1024
#define HH 2048
#define II 4096
#define NN 16
#define RR 128
#define BL (BB*LL)          // 2048
#define SSMW (RR + 2*NN)    // 160
#define SPLITK 8

// ---------------- scratch (device globals) ----------------
__device__ float  g_proj[(size_t)BL * 2 * II];          // [BL, 8192] h_in | gate (fp32)
__device__ float  g_u   [(size_t)BL * II];              // fp32 for scan
__device__ float  g_part[(size_t)SPLITK * BL * SSMW];   // split-K partials
__device__ float  g_ssm [(size_t)BL * SSMW];            // fp32 for scan (B, C)
__device__ float  g_dt  [(size_t)BL * II];              // fp32 for scan
__device__ __half h_x   [(size_t)BL * HH];              // fp16 inputs for GEMMs
__device__ __half h_w1  [(size_t)2 * II * HH];
__device__ __half h_wx  [(size_t)SSMW * II];
__device__ __half h_wdt [(size_t)II * RR];
__device__ __half h_wo  [(size_t)HH * II];
__device__ __half h_u   [(size_t)BL * II];
__device__ __half h_ssm [(size_t)BL * SSMW];
__device__ __half h_y   [(size_t)BL * II];

// ---------------- helpers ----------------
__device__ __forceinline__ uint32_t smem_u32(const void* p) {
    uint32_t a;
    asm("{ .reg .u64 t; cvta.to.shared.u64 t, %1; cvt.u32.u64 %0, t; }" : "=r"(a) : "l"(p));
    return a;
}
__device__ __forceinline__ uint32_t swz(uint32_t off) {   // SW128: bits[6:4] ^= bits[9:7]
    return off ^ ((off >> 3) & 0x70);
}
#define CP_ASYNC16(dst, src) \
    asm volatile("cp.async.cg.shared.global [%0], [%1], 16;" :: "r"(dst), "l"(src) : "memory")
#define CP_COMMIT() asm volatile("cp.async.commit_group;" ::: "memory")
#define CP_WAIT0()  asm volatile("cp.async.wait_group 0;" ::: "memory")
#define CP_WAIT1()  asm volatile("cp.async.wait_group 1;" ::: "memory")
#define CP_WAIT2()  asm volatile("cp.async.wait_group 2;" ::: "memory")

#define LDMATRIX_X4(r, addr) \
    asm volatile("ldmatrix.sync.aligned.m8n8.x4.shared.b16 {%0,%1,%2,%3}, [%4];" \
        : "=r"((r)[0]), "=r"((r)[1]), "=r"((r)[2]), "=r"((r)[3]) : "r"(addr))

#define MMA_F16(d, a, b0, b1) \
    asm volatile("mma.sync.aligned.m16n8k16.row.col.f32.f16.f16.f32 " \
        "{%0,%1,%2,%3}, {%4,%5,%6,%7}, {%8,%9}, {%0,%1,%2,%3};" \
        : "+f"((d)[0]), "+f"((d)[1]), "+f"((d)[2]), "+f"((d)[3]) \
        : "r"((a)[0]), "r"((a)[1]), "r"((a)[2]), "r"((a)[3]), "r"(b0), "r"(b1))

// ---------------------------------------------------------------------------
// fp16 tensor-core GEMM:  C[M,N] = A[M,K] * B[N,K]^T  (fp16 in, fp32 accum/out)
// CTA tile 128x128, BK=64 halves (128B rows), 128 threads = 4 warps @ 64x64.
// 3-stage cp.async pipeline, SW128 swizzle, 2 CTAs/SM (96 KB smem each).
// M % 128 == 0, K % 64 == 0, N ragged. Split-K: A/B += z*akz, C += z*ckz.
// EPI: 0 = store fp32, 1 = softplus(acc + bias[n])
// ---------------------------------------------------------------------------
template<int EPI>
__global__ __launch_bounds__(128, 2)
void hgemm(const __half* __restrict__ A, const __half* __restrict__ B,
           float* __restrict__ C, const float* __restrict__ bias,
           int N, int K, int lda, int ldb, int ldc, int akz, long long ckz)
{
    extern __shared__ __align__(1024) char smem[];
    constexpr int ATILE = 128 * 128;             // 16 KB (128 rows x 128B)
    constexpr int STAGE = 2 * ATILE;             // A + B = 32 KB
    const uint32_t sb = smem_u32(smem);
    const int tid = threadIdx.x;
    const int brow = blockIdx.y * 128;
    const int bcol = blockIdx.x * 128;

    A += (size_t)blockIdx.z * akz;
    B += (size_t)blockIdx.z * akz;
    C += (size_t)blockIdx.z * ckz;

    auto load_tile = [&](int kt, int s) {
        uint32_t base = sb + s * STAGE;
        const __half* Ab = A + (size_t)brow * lda + kt * 64;
#pragma unroll
        for (int i = 0; i < 8; ++i) {
            int t = tid + 128 * i;               // 0..1023 -> 128 rows x 8 chunks
            int r = t >> 3, c = (t & 7) * 16;    // byte col in 128B row
            CP_ASYNC16(base + swz(r * 128 + c), Ab + (size_t)r * lda + (c >> 1));
        }
        const __half* Bb = B + (size_t)bcol * ldb + kt * 64;
        uint32_t bb = base + ATILE;
#pragma unroll
        for (int i = 0; i < 8; ++i) {
            int t = tid + 128 * i;
            int r = t >> 3, c = (t & 7) * 16;
            uint32_t d = bb + swz(r * 128 + c);
            if (bcol + r < N) {
                CP_ASYNC16(d, Bb + (size_t)r * ldb + (c >> 1));
            } else {
                *(float4*)(smem + (d - sb)) = make_float4(0.f, 0.f, 0.f, 0.f);
            }
        }
        CP_COMMIT();
    };

    const int nt = K / 64;
    float acc[4][8][4];
#pragma unroll
    for (int mf = 0; mf < 4; ++mf)
#pragma unroll
        for (int nf = 0; nf < 8; ++nf)
#pragma unroll
            for (int q = 0; q < 4; ++q) acc[mf][nf][q] = 0.f;

    const int w = tid >> 5, lane = tid & 31;
    const int wm = (w & 1) * 64;            // 2 warps along M
    const int wn = (w >> 1) * 64;           // 2 warps along N
    const int g = lane >> 3, rr = lane & 7;
    const int arow = (g & 1) * 8 + rr;      // A-frag row in 16, k-byte half below
    const int abyte = (g >> 1) * 16;
    const int brw = (g >> 1) * 8 + rr;      // B-frag: n-row in 16, k-byte half
    const int bbyte = (g & 1) * 16;

    load_tile(0, 0);
    if (nt > 1) load_tile(1, 1);

    for (int kt = 0; kt < nt; ++kt) {
        if (kt + 2 < nt) { load_tile(kt + 2, (kt + 2) % 3); CP_WAIT2(); }
        else if (kt + 1 < nt) { CP_WAIT1(); }
        else { CP_WAIT0(); }
        __syncthreads();
        uint32_t abase = sb + (kt % 3) * STAGE;
        uint32_t bbase = abase + ATILE;
#pragma unroll
        for (int ks = 0; ks < 4; ++ks) {        // 4 x k16 (32B each)
            uint32_t af[4][4], bf[4][4];
#pragma unroll
            for (int mf = 0; mf < 4; ++mf)
                LDMATRIX_X4(af[mf], abase + swz((wm + mf * 16 + arow) * 128 + ks * 32 + abyte));
#pragma unroll
            for (int pp = 0; pp < 4; ++pp)      // pairs of n8-groups (16 n each)
                LDMATRIX_X4(bf[pp], bbase + swz((wn + pp * 16 + brw) * 128 + ks * 32 + bbyte));
#pragma unroll
            for (int mf = 0; mf < 4; ++mf)
#pragma unroll
                for (int pp = 0; pp < 4; ++pp) {
                    MMA_F16(acc[mf][2 * pp],     af[mf], bf[pp][0], bf[pp][1]);
                    MMA_F16(acc[mf][2 * pp + 1], af[mf], bf[pp][2], bf[pp][3]);
                }
        }
        __syncthreads();
    }

    // epilogue
    const int gid = lane >> 2, tig = lane & 3;
#pragma unroll
    for (int mf = 0; mf < 4; ++mf) {
#pragma unroll
        for (int nf = 0; nf < 8; ++nf) {
            int n = bcol + wn + nf * 8 + tig * 2;
            if (n >= N) continue;
            int m0 = brow + wm + mf * 16 + gid;
            float v[4] = { acc[mf][nf][0], acc[mf][nf][1], acc[mf][nf][2], acc[mf][nf][3] };
            if (EPI == 1) {
#pragma unroll
                for (int q = 0; q < 4; ++q) {
                    float t = v[q] + bias[n + (q & 1)];
                    v[q] = (t > 20.f) ? t : log1pf(__expf(t));
                }
            }
            *(float2*)(C + (size_t)m0 * ldc + n)       = make_float2(v[0], v[1]);
            *(float2*)(C + (size_t)(m0 + 8) * ldc + n) = make_float2(v[2], v[3]);
        }
    }
}

// ---------------------------------------------------------------------------
// f32 -> f16 conversion
// ---------------------------------------------------------------------------
__global__ __launch_bounds__(256)
void cvt_f16_kernel(const float4* __restrict__ src, __half2* __restrict__ dst, int n4)
{
    int i = blockIdx.x * blockDim.x + threadIdx.x;
    if (i < n4) {
        float4 v = src[i];
        dst[2 * i]     = __floats2half2_rn(v.x, v.y);
        dst[2 * i + 1] = __floats2half2_rn(v.z, v.w);
    }
}

// ---------------------------------------------------------------------------
// split-K reduce for ssm (fp32 + fp16 outputs)
// ---------------------------------------------------------------------------
__global__ __launch_bounds__(256)
void reduce_ssm_kernel()
{
    int i = blockIdx.x * blockDim.x + threadIdx.x;
    const int n = BL * SSMW;
    if (i < n) {
        float s = 0.f;
#pragma unroll
        for (int z = 0; z < SPLITK; ++z) s += g_part[(size_t)z * n + i];
        g_ssm[i] = s;
        h_ssm[i] = __float2half_rn(s);
    }
}

// ---------------------------------------------------------------------------
// Causal depthwise conv (K=4) + bias + silu -> u (fp32 + fp16)
// ---------------------------------------------------------------------------
__global__ __launch_bounds__(256)
void conv_silu_kernel(const float* __restrict__ conv_w, const float* __restrict__ conv_b)
{
    int idx = blockIdx.x * blockDim.x + threadIdx.x;
    if (idx >= BL * II) return;
    int i  = idx & (II - 1);
    int bl = idx >> 12;
    int l  = bl & (LL - 1);

    float w0 = conv_w[i * 4 + 0];
    float w1 = conv_w[i * 4 + 1];
    float w2 = conv_w[i * 4 + 2];
    float w3 = conv_w[i * 4 + 3];

    const float* hp = g_proj + (size_t)bl * (2 * II) + i;
    float acc = conv_b[i];
    if (l >= 3) acc += w0 * hp[-(ptrdiff_t)3 * 2 * II];
    if (l >= 2) acc += w1 * hp[-(ptrdiff_t)2 * 2 * II];
    if (l >= 1) acc += w2 * hp[-(ptrdiff_t)1 * 2 * II];
    acc += w3 * hp[0];

    float sig = 1.f / (1.f + __expf(-acc));
    float v = acc * sig;
    g_u[idx] = v;
    h_u[idx] = __float2half_rn(v);
}

// ---------------------------------------------------------------------------
// Selective scan -> y (fp16 for GEMM6)
// ---------------------------------------------------------------------------
__global__ __launch_bounds__(256)
void scan_kernel(const float* __restrict__ A_log, const float* __restrict__ D)
{
    int g = blockIdx.x * 16 + (threadIdx.x >> 4);
    int lane = threadIdx.x & 15;
    int i = g & (II - 1);
    int b = g >> 12;

    float a_n  = -__expf(A_log[i * NN + lane]);
    float Dval = D[i];

    const float* dtp = g_dt + (size_t)b * LL * II + i;
    const float* up  = g_u  + (size_t)b * LL * II + i;
    const float* gp  = g_proj + (size_t)b * LL * (2 * II) + II + i;
    const float* sp  = g_ssm + (size_t)b * LL * SSMW;
    __half* yp = h_y + (size_t)b * LL * II + i;

    float h = 0.f;
    for (int l = 0; l < LL; ++l) {
        float dt = dtp[(size_t)l * II];
        float u  = up [(size_t)l * II];
        float gt = gp [(size_t)l * 2 * II];
        float Bn = sp[(size_t)l * SSMW + RR + lane];
        float Cn = sp[(size_t)l * SSMW + RR + NN + lane];

        float dA = __expf(dt * a_n);
        h = dA * h + (dt * u) * Bn;
        float contrib = h * Cn;
        contrib += __shfl_xor_sync(0xffffffffu, contrib, 8, 16);
        contrib += __shfl_xor_sync(0xffffffffu, contrib, 4, 16);
        contrib += __shfl_xor_sync(0xffffffffu, contrib, 2, 16);
        contrib += __shfl_xor_sync(0xffffffffu, contrib, 1, 16);
        if (lane == 0) {
            float y = contrib + Dval * u;
            float sg = gt / (1.f + __expf(-gt));
            yp[(size_t)l * II] = __float2half_rn(y * sg);
        }
    }
}

// ---------------------------------------------------------------------------
extern "C" void kernel_launch(void* const* d_in, const int* in_sizes, int n_in,
                              void* d_out, int out_size)
{
    const float* x          = (const float*)d_in[0];
    const float* in_proj_w  = (const float*)d_in[1];
    const float* conv_w     = (const float*)d_in[2];
    const float* conv_b     = (const float*)d_in[3];
    const float* x_proj_w   = (const float*)d_in[4];
    const float* dt_proj_w  = (const float*)d_in[5];
    const float* dt_proj_b  = (const float*)d_in[6];
    const float* A_log      = (const float*)d_in[7];
    const float* Dw         = (const float*)d_in[8];
    const float* out_proj_w = (const float*)d_in[9];
    float* out = (float*)d_out;

    float *p_proj, *p_part, *p_dt;
    __half *ph_x, *ph_w1, *ph_wx, *ph_wdt, *ph_wo, *ph_u, *ph_ssm, *ph_y;
    cudaGetSymbolAddress((void**)&p_proj, g_proj);
    cudaGetSymbolAddress((void**)&p_part, g_part);
    cudaGetSymbolAddress((void**)&p_dt,   g_dt);
    cudaGetSymbolAddress((void**)&ph_x,   h_x);
    cudaGetSymbolAddress((void**)&ph_w1,  h_w1);
    cudaGetSymbolAddress((void**)&ph_wx,  h_wx);
    cudaGetSymbolAddress((void**)&ph_wdt, h_wdt);
    cudaGetSymbolAddress((void**)&ph_wo,  h_wo);
    cudaGetSymbolAddress((void**)&ph_u,   h_u);
    cudaGetSymbolAddress((void**)&ph_ssm, h_ssm);
    cudaGetSymbolAddress((void**)&ph_y,   h_y);

    const int smem = 98304;   // 3 stages x 32 KB
    cudaFuncSetAttribute(hgemm<0>, cudaFuncAttributeMaxDynamicSharedMemorySize, smem);
    cudaFuncSetAttribute(hgemm<1>, cudaFuncAttributeMaxDynamicSharedMemorySize, smem);

    // convert GEMM inputs to fp16 (RN)
    auto cvt = [&](const float* s, __half* d, size_t n) {
        int n4 = (int)(n / 4);
        cvt_f16_kernel<<<(n4 + 255) / 256, 256>>>((const float4*)s, (__half2*)d, n4);
    };
    cvt(x,          ph_x,   (size_t)BL * HH);
    cvt(in_proj_w,  ph_w1,  (size_t)2 * II * HH);
    cvt(x_proj_w,   ph_wx,  (size_t)SSMW * II);
    cvt(dt_proj_w,  ph_wdt, (size_t)II * RR);
    cvt(out_proj_w, ph_wo,  (size_t)HH * II);

    // 1) proj = x @ in_proj_w^T   [2048, 8192], K=2048
    hgemm<0><<<dim3(2 * II / 128, BL / 128, 1), 128, smem>>>(
        ph_x, ph_w1, p_proj, nullptr, 2 * II, HH, HH, HH, 2 * II, 0, 0);
    // 2) conv + silu -> u (fp32 + fp16)
    conv_silu_kernel<<<(BL * II + 255) / 256, 256>>>(conv_w, conv_b);
    // 3) ssm = u @ x_proj_w^T   [2048, 160], K=4096, split-K=8
    hgemm<0><<<dim3((SSMW + 127) / 128, BL / 128, SPLITK), 128, smem>>>(
        ph_u, ph_wx, p_part, nullptr, SSMW, II / SPLITK, II, II, SSMW,
        II / SPLITK, (long long)BL * SSMW);
    reduce_ssm_kernel<<<(BL * SSMW + 255) / 256, 256>>>();
    // 4) dt = softplus(ts @ dt_proj_w^T + bias)   [2048, 4096], K=128, lda=160
    hgemm<1><<<dim3(II / 128, BL / 128, 1), 128, smem>>>(
        ph_ssm, ph_wdt, p_dt, dt_proj_b, II, RR, SSMW, RR, II, 0, 0);
    // 5) selective scan -> y (fp16)
    scan_kernel<<<(BB * II) / 16, 256>>>(A_log, Dw);
    // 6) out = y @ out_proj_w^T   [2048, 2048], K=4096
    hgemm<0><<<dim3(HH / 128, BL / 128, 1), 128, smem>>>(
        ph_y, ph_wo, out, nullptr, HH, II, II, II, HH, 0, 0);
}

// round 17
// speedup vs baseline: 5.6051x; 1.9051x over previous
#include <cuda_runtime.h>
#include <cuda_fp16.h>
#include <cstdint>

// ---------------- problem constants ----------------
#define BB 2
#define LL 1024
#define HH 2048
#define II 4096
#define NN 16
#define RR 128
#define BL (BB*LL)          // 2048
#define SSMW (RR + 2*NN)    // 160
#define SPLITK 8
#define CH 32               // scan l-chunk

// ---------------- scratch (device globals) ----------------
__device__ float  g_proj[(size_t)BL * 2 * II];          // [BL, 8192] h_in | gate (fp32)
__device__ float  g_u   [(size_t)BL * II];              // fp32 for scan
__device__ float  g_part[(size_t)SPLITK * BL * SSMW];   // split-K partials
__device__ float  g_ssm [(size_t)BL * SSMW];            // fp32 for scan (B, C)
__device__ float  g_dt  [(size_t)BL * II];              // fp32 for scan
__device__ __half h_x   [(size_t)BL * HH];              // fp16 inputs for GEMMs
__device__ __half h_w1  [(size_t)2 * II * HH];
__device__ __half h_wx  [(size_t)SSMW * II];
__device__ __half h_wdt [(size_t)II * RR];
__device__ __half h_wo  [(size_t)HH * II];
__device__ __half h_u   [(size_t)BL * II];
__device__ __half h_ssm [(size_t)BL * SSMW];
__device__ __half h_y   [(size_t)BL * II];

// ---------------- helpers ----------------
__device__ __forceinline__ uint32_t smem_u32(const void* p) {
    uint32_t a;
    asm("{ .reg .u64 t; cvta.to.shared.u64 t, %1; cvt.u32.u64 %0, t; }" : "=r"(a) : "l"(p));
    return a;
}
__device__ __forceinline__ uint32_t swz(uint32_t off) {   // SW128: bits[6:4] ^= bits[9:7]
    return off ^ ((off >> 3) & 0x70);
}
#define CP_ASYNC16(dst, src) \
    asm volatile("cp.async.cg.shared.global [%0], [%1], 16;" :: "r"(dst), "l"(src) : "memory")
#define CP_COMMIT() asm volatile("cp.async.commit_group;" ::: "memory")
#define CP_WAIT0()  asm volatile("cp.async.wait_group 0;" ::: "memory")
#define CP_WAIT1()  asm volatile("cp.async.wait_group 1;" ::: "memory")
#define CP_WAIT2()  asm volatile("cp.async.wait_group 2;" ::: "memory")

#define LDMATRIX_X4(r, addr) \
    asm volatile("ldmatrix.sync.aligned.m8n8.x4.shared.b16 {%0,%1,%2,%3}, [%4];" \
        : "=r"((r)[0]), "=r"((r)[1]), "=r"((r)[2]), "=r"((r)[3]) : "r"(addr))

#define MMA_F16(d, a, b0, b1) \
    asm volatile("mma.sync.aligned.m16n8k16.row.col.f32.f16.f16.f32 " \
        "{%0,%1,%2,%3}, {%4,%5,%6,%7}, {%8,%9}, {%0,%1,%2,%3};" \
        : "+f"((d)[0]), "+f"((d)[1]), "+f"((d)[2]), "+f"((d)[3]) \
        : "r"((a)[0]), "r"((a)[1]), "r"((a)[2]), "r"((a)[3]), "r"(b0), "r"(b1))

// ---------------------------------------------------------------------------
// fp16 tensor-core GEMM:  C[M,N] = A[M,K] * B[N,K]^T  (fp16 in, fp32 accum/out)
// CTA tile 128x128, BK=64 halves, 128 threads = 4 warps @ 64x64,
// 3-stage cp.async, SW128, 2 CTAs/SM. Split-K via blockIdx.z.
// EPI: 0 = store fp32, 1 = softplus(acc + bias[n])
// ---------------------------------------------------------------------------
template<int EPI>
__global__ __launch_bounds__(128, 2)
void hgemm(const __half* __restrict__ A, const __half* __restrict__ B,
           float* __restrict__ C, const float* __restrict__ bias,
           int N, int K, int lda, int ldb, int ldc, int akz, long long ckz)
{
    extern __shared__ __align__(1024) char smem[];
    constexpr int ATILE = 128 * 128;
    constexpr int STAGE = 2 * ATILE;
    const uint32_t sb = smem_u32(smem);
    const int tid = threadIdx.x;
    const int brow = blockIdx.y * 128;
    const int bcol = blockIdx.x * 128;

    A += (size_t)blockIdx.z * akz;
    B += (size_t)blockIdx.z * akz;
    C += (size_t)blockIdx.z * ckz;

    auto load_tile = [&](int kt, int s) {
        uint32_t base = sb + s * STAGE;
        const __half* Ab = A + (size_t)brow * lda + kt * 64;
#pragma unroll
        for (int i = 0; i < 8; ++i) {
            int t = tid + 128 * i;
            int r = t >> 3, c = (t & 7) * 16;
            CP_ASYNC16(base + swz(r * 128 + c), Ab + (size_t)r * lda + (c >> 1));
        }
        const __half* Bb = B + (size_t)bcol * ldb + kt * 64;
        uint32_t bb = base + ATILE;
#pragma unroll
        for (int i = 0; i < 8; ++i) {
            int t = tid + 128 * i;
            int r = t >> 3, c = (t & 7) * 16;
            uint32_t d = bb + swz(r * 128 + c);
            if (bcol + r < N) {
                CP_ASYNC16(d, Bb + (size_t)r * ldb + (c >> 1));
            } else {
                *(float4*)(smem + (d - sb)) = make_float4(0.f, 0.f, 0.f, 0.f);
            }
        }
        CP_COMMIT();
    };

    const int nt = K / 64;
    float acc[4][8][4];
#pragma unroll
    for (int mf = 0; mf < 4; ++mf)
#pragma unroll
        for (int nf = 0; nf < 8; ++nf)
#pragma unroll
            for (int q = 0; q < 4; ++q) acc[mf][nf][q] = 0.f;

    const int w = tid >> 5, lane = tid & 31;
    const int wm = (w & 1) * 64;
    const int wn = (w >> 1) * 64;
    const int g = lane >> 3, rr = lane & 7;
    const int arow = (g & 1) * 8 + rr;
    const int abyte = (g >> 1) * 16;
    const int brw = (g >> 1) * 8 + rr;
    const int bbyte = (g & 1) * 16;

    load_tile(0, 0);
    if (nt > 1) load_tile(1, 1);

    for (int kt = 0; kt < nt; ++kt) {
        if (kt + 2 < nt) { load_tile(kt + 2, (kt + 2) % 3); CP_WAIT2(); }
        else if (kt + 1 < nt) { CP_WAIT1(); }
        else { CP_WAIT0(); }
        __syncthreads();
        uint32_t abase = sb + (kt % 3) * STAGE;
        uint32_t bbase = abase + ATILE;
#pragma unroll
        for (int ks = 0; ks < 4; ++ks) {
            uint32_t af[4][4], bf[4][4];
#pragma unroll
            for (int mf = 0; mf < 4; ++mf)
                LDMATRIX_X4(af[mf], abase + swz((wm + mf * 16 + arow) * 128 + ks * 32 + abyte));
#pragma unroll
            for (int pp = 0; pp < 4; ++pp)
                LDMATRIX_X4(bf[pp], bbase + swz((wn + pp * 16 + brw) * 128 + ks * 32 + bbyte));
#pragma unroll
            for (int mf = 0; mf < 4; ++mf)
#pragma unroll
                for (int pp = 0; pp < 4; ++pp) {
                    MMA_F16(acc[mf][2 * pp],     af[mf], bf[pp][0], bf[pp][1]);
                    MMA_F16(acc[mf][2 * pp + 1], af[mf], bf[pp][2], bf[pp][3]);
                }
        }
        __syncthreads();
    }

    const int gid = lane >> 2, tig = lane & 3;
#pragma unroll
    for (int mf = 0; mf < 4; ++mf) {
#pragma unroll
        for (int nf = 0; nf < 8; ++nf) {
            int n = bcol + wn + nf * 8 + tig * 2;
            if (n >= N) continue;
            int m0 = brow + wm + mf * 16 + gid;
            float v[4] = { acc[mf][nf][0], acc[mf][nf][1], acc[mf][nf][2], acc[mf][nf][3] };
            if (EPI == 1) {
#pragma unroll
                for (int q = 0; q < 4; ++q) {
                    float t = v[q] + bias[n + (q & 1)];
                    v[q] = (t > 20.f) ? t : log1pf(__expf(t));
                }
            }
            *(float2*)(C + (size_t)m0 * ldc + n)       = make_float2(v[0], v[1]);
            *(float2*)(C + (size_t)(m0 + 8) * ldc + n) = make_float2(v[2], v[3]);
        }
    }
}

// ---------------------------------------------------------------------------
// single fused f32 -> f16 conversion over all 5 GEMM inputs
// ---------------------------------------------------------------------------
__global__ __launch_bounds__(256)
void cvt_all_kernel(const float4* __restrict__ x, const float4* __restrict__ w1,
                    const float4* __restrict__ wx, const float4* __restrict__ wdt,
                    const float4* __restrict__ wo)
{
    const int c1 = (BL * HH) / 4;
    const int c2 = c1 + (2 * II * HH) / 4;
    const int c3 = c2 + (SSMW * II) / 4;
    const int c4 = c3 + (II * RR) / 4;
    const int c5 = c4 + (HH * II) / 4;
    int i = blockIdx.x * blockDim.x + threadIdx.x;
    if (i >= c5) return;
    const float4* s; __half2* d; int off;
    if (i < c1)      { s = x;   d = (__half2*)h_x;   off = i; }
    else if (i < c2) { s = w1;  d = (__half2*)h_w1;  off = i - c1; }
    else if (i < c3) { s = wx;  d = (__half2*)h_wx;  off = i - c2; }
    else if (i < c4) { s = wdt; d = (__half2*)h_wdt; off = i - c3; }
    else             { s = wo;  d = (__half2*)h_wo;  off = i - c4; }
    float4 v = s[off];
    d[2 * off]     = __floats2half2_rn(v.x, v.y);
    d[2 * off + 1] = __floats2half2_rn(v.z, v.w);
}

// ---------------------------------------------------------------------------
// split-K reduce for ssm (fp32 + fp16 outputs)
// ---------------------------------------------------------------------------
__global__ __launch_bounds__(256)
void reduce_ssm_kernel()
{
    int i = blockIdx.x * blockDim.x + threadIdx.x;
    const int n = BL * SSMW;
    if (i < n) {
        float s = 0.f;
#pragma unroll
        for (int z = 0; z < SPLITK; ++z) s += g_part[(size_t)z * n + i];
        g_ssm[i] = s;
        h_ssm[i] = __float2half_rn(s);
    }
}

// ---------------------------------------------------------------------------
// Causal depthwise conv (K=4) + bias + silu -> u (fp32 + fp16)
// ---------------------------------------------------------------------------
__global__ __launch_bounds__(256)
void conv_silu_kernel(const float* __restrict__ conv_w, const float* __restrict__ conv_b)
{
    int idx = blockIdx.x * blockDim.x + threadIdx.x;
    if (idx >= BL * II) return;
    int i  = idx & (II - 1);
    int bl = idx >> 12;
    int l  = bl & (LL - 1);

    float w0 = conv_w[i * 4 + 0];
    float w1 = conv_w[i * 4 + 1];
    float w2 = conv_w[i * 4 + 2];
    float w3 = conv_w[i * 4 + 3];

    const float* hp = g_proj + (size_t)bl * (2 * II) + i;
    float acc = conv_b[i];
    if (l >= 3) acc += w0 * hp[-(ptrdiff_t)3 * 2 * II];
    if (l >= 2) acc += w1 * hp[-(ptrdiff_t)2 * 2 * II];
    if (l >= 1) acc += w2 * hp[-(ptrdiff_t)1 * 2 * II];
    acc += w3 * hp[0];

    float sig = 1.f / (1.f + __expf(-acc));
    float v = acc * sig;
    g_u[idx] = v;
    h_u[idx] = __float2half_rn(v);
}

// ---------------------------------------------------------------------------
// Tiled selective scan -> y (fp16). Block = 256 threads = 16 groups of 16
// lanes; handles 16 consecutive i for one batch. l processed in CH-chunks
// staged through smem with coalesced loads/stores.
// ---------------------------------------------------------------------------
__global__ __launch_bounds__(256)
void scan_kernel(const float* __restrict__ A_log, const float* __restrict__ D)
{
    __shared__ float  sdt[CH][16];
    __shared__ float  su [CH][16];
    __shared__ float  sg [CH][16];
    __shared__ float  sB [CH][16];
    __shared__ float  sC [CH][16];
    __shared__ __half sy [CH][16];

    const int blk = blockIdx.x;           // 0..511
    const int b   = blk >> 8;             // 256 blocks per batch (4096/16)
    const int i0  = (blk & 255) << 4;
    const int tid = threadIdx.x;
    const int grp = tid >> 4, lane = tid & 15;
    const int i   = i0 + grp;

    const float a_n  = -__expf(A_log[i * NN + lane]);
    const float Dval = D[i];
    const size_t base = (size_t)b * LL;

    float h = 0.f;
    for (int l0 = 0; l0 < LL; l0 += CH) {
        // coalesced load phase
        for (int e = tid; e < CH * 16; e += 256) {
            int r = e >> 4, c = e & 15;
            size_t row = base + l0 + r;
            sdt[r][c] = g_dt [row * II + i0 + c];
            su [r][c] = g_u  [row * II + i0 + c];
            sg [r][c] = g_proj[row * (2 * II) + II + i0 + c];
        }
        for (int e = tid; e < CH * 32; e += 256) {
            int r = e >> 5, c = e & 31;
            float v = g_ssm[(base + l0 + r) * SSMW + RR + c];
            if (c < 16) sB[r][c] = v; else sC[r][c - 16] = v;
        }
        __syncthreads();
        // serial recurrence from smem
        for (int r = 0; r < CH; ++r) {
            float dt = sdt[r][grp];
            float u  = su [r][grp];
            float Bn = sB [r][lane];
            float Cn = sC [r][lane];
            float dA = __expf(dt * a_n);
            h = dA * h + (dt * u) * Bn;
            float contrib = h * Cn;
            contrib += __shfl_xor_sync(0xffffffffu, contrib, 8, 16);
            contrib += __shfl_xor_sync(0xffffffffu, contrib, 4, 16);
            contrib += __shfl_xor_sync(0xffffffffu, contrib, 2, 16);
            contrib += __shfl_xor_sync(0xffffffffu, contrib, 1, 16);
            if (lane == 0) {
                float gt = sg[r][grp];
                float sgm = gt / (1.f + __expf(-gt));
                sy[r][grp] = __float2half_rn((contrib + Dval * u) * sgm);
            }
        }
        __syncthreads();
        // coalesced y store
        for (int e = tid; e < CH * 16; e += 256) {
            int r = e >> 4, c = e & 15;
            h_y[(base + l0 + r) * II + i0 + c] = sy[r][c];
        }
        __syncthreads();
    }
}

// ---------------------------------------------------------------------------
extern "C" void kernel_launch(void* const* d_in, const int* in_sizes, int n_in,
                              void* d_out, int out_size)
{
    const float* x          = (const float*)d_in[0];
    const float* in_proj_w  = (const float*)d_in[1];
    const float* conv_w     = (const float*)d_in[2];
    const float* conv_b     = (const float*)d_in[3];
    const float* x_proj_w   = (const float*)d_in[4];
    const float* dt_proj_w  = (const float*)d_in[5];
    const float* dt_proj_b  = (const float*)d_in[6];
    const float* A_log      = (const float*)d_in[7];
    const float* Dw         = (const float*)d_in[8];
    const float* out_proj_w = (const float*)d_in[9];
    float* out = (float*)d_out;

    float *p_proj, *p_part, *p_dt;
    __half *ph_x, *ph_w1, *ph_wx, *ph_wdt, *ph_wo, *ph_u, *ph_ssm, *ph_y;
    cudaGetSymbolAddress((void**)&p_proj, g_proj);
    cudaGetSymbolAddress((void**)&p_part, g_part);
    cudaGetSymbolAddress((void**)&p_dt,   g_dt);
    cudaGetSymbolAddress((void**)&ph_x,   h_x);
    cudaGetSymbolAddress((void**)&ph_w1,  h_w1);
    cudaGetSymbolAddress((void**)&ph_wx,  h_wx);
    cudaGetSymbolAddress((void**)&ph_wdt, h_wdt);
    cudaGetSymbolAddress((void**)&ph_wo,  h_wo);
    cudaGetSymbolAddress((void**)&ph_u,   h_u);
    cudaGetSymbolAddress((void**)&ph_ssm, h_ssm);
    cudaGetSymbolAddress((void**)&ph_y,   h_y);

    const int smem = 98304;   // 3 stages x 32 KB
    cudaFuncSetAttribute(hgemm<0>, cudaFuncAttributeMaxDynamicSharedMemorySize, smem);
    cudaFuncSetAttribute(hgemm<1>, cudaFuncAttributeMaxDynamicSharedMemorySize, smem);

    // fused fp16 conversion of all GEMM inputs
    {
        const int total4 = (BL * HH + 2 * II * HH + SSMW * II + II * RR + HH * II) / 4;
        cvt_all_kernel<<<(total4 + 255) / 256, 256>>>(
            (const float4*)x, (const float4*)in_proj_w, (const float4*)x_proj_w,
            (const float4*)dt_proj_w, (const float4*)out_proj_w);
    }

    // 1) proj = x @ in_proj_w^T   [2048, 8192], K=2048
    hgemm<0><<<dim3(2 * II / 128, BL / 128, 1), 128, smem>>>(
        ph_x, ph_w1, p_proj, nullptr, 2 * II, HH, HH, HH, 2 * II, 0, 0);
    // 2) conv + silu -> u (fp32 + fp16)
    conv_silu_kernel<<<(BL * II + 255) / 256, 256>>>(conv_w, conv_b);
    // 3) ssm = u @ x_proj_w^T   [2048, 160], K=4096, split-K=8
    hgemm<0><<<dim3((SSMW + 127) / 128, BL / 128, SPLITK), 128, smem>>>(
        ph_u, ph_wx, p_part, nullptr, SSMW, II / SPLITK, II, II, SSMW,
        II / SPLITK, (long long)BL * SSMW);
    reduce_ssm_kernel<<<(BL * SSMW + 255) / 256, 256>>>();
    // 4) dt = softplus(ts @ dt_proj_w^T + bias)   [2048, 4096], K=128, lda=160
    hgemm<1><<<dim3(II / 128, BL / 128, 1), 128, smem>>>(
        ph_ssm, ph_wdt, p_dt, dt_proj_b, II, RR, SSMW, RR, II, 0, 0);
    // 5) tiled selective scan -> y (fp16)
    scan_kernel<<<512, 256>>>(A_log, Dw);
    // 6) out = y @ out_proj_w^T   [2048, 2048], K=4096
    hgemm<0><<<dim3(HH / 128, BL / 128, 1), 128, smem>>>(
        ph_y, ph_wo, out, nullptr, HH, II, II, II, HH, 0, 0);
}